// round 1
// baseline (speedup 1.0000x reference)
#include <cuda_runtime.h>

// ---------------------------------------------------------------------------
// Fused Goal_Conditioned_Policies forward: one CTA per sample (B = 4096).
// conv1(3->32,s2) -> relu -> conv2(32->64,s2) -> relu -> meanpool -> MLP -> softmax
// All intermediates live in shared memory. fp32 throughout.
// ---------------------------------------------------------------------------

#define B_SAMPLES 4096
#define NVAR      50
#define NTHREADS  256

// ---- shared memory layout (in floats) ----
#define XS_OFF   0                    // [3][66][67] zero-padded swizzled input
#define XS_SZ    (3 * 66 * 67)        // 13266
#define H1_OFF   (XS_OFF + XS_SZ)     // [32][34][35] zero-padded swizzled conv1 out
#define H1_SZ    (32 * 34 * 35)       // 38080
#define CS_OFF   (H1_OFF + H1_SZ)     // C[b] tile 50x50
#define CS_SZ    2500
#define WS1_OFF  (CS_OFF + CS_SZ)     // conv1 weights 32*3*9
#define WS1_SZ   864
#define B1_OFF   (WS1_OFF + WS1_SZ)
#define B2_OFF   (B1_OFF + 32)
#define POOL_OFF (B2_OFF + 64)        // pooled [64]
#define X1_OFF   (POOL_OFF + 64)      // [128]
#define X2_OFF   (X1_OFF + 128)       // [50] (pad 64)
#define E_OFF    (X2_OFF + 64)        // [50] (pad 64)
#define X3_OFF   (E_OFF + 64)         // [128]
#define X5_OFF   (X3_OFF + 128)       // [64]
#define X6_OFF   (X5_OFF + 64)        // [64]
#define X7_OFF   (X6_OFF + 64)        // [64]
#define LG_OFF   (X7_OFF + 64)        // [50] (pad 64)
#define RED_OFF  (LG_OFF + 64)        // [4]
#define SMEM_FLOATS (RED_OFF + 4)
#define SMEM_BYTES  (SMEM_FLOATS * 4)

__device__ __forceinline__ int xs_idx(int ic, int r, int c) {
    // swizzle column bit0 by (c>>5)&1 so stride-2 warp loads are conflict-free
    return XS_OFF + ic * (66 * 67) + r * 67 + (c ^ ((c >> 5) & 1));
}
__device__ __forceinline__ int h1_idx(int ch, int r, int c) {
    // swizzle column bit0 by (r>>1)&1: half-warps hitting rows r and r+2
    // land on opposite bank parities -> conflict-free stride-2 access
    return H1_OFF + ch * (34 * 35) + r * 35 + (c ^ ((r >> 1) & 1));
}

__global__ __launch_bounds__(NTHREADS, 1)
void gcp_fused_kernel(const float* __restrict__ x,    const float* __restrict__ C,
                      const float* __restrict__ w1,   const float* __restrict__ b1,
                      const float* __restrict__ w2,   const float* __restrict__ b2,
                      const float* __restrict__ encw, const float* __restrict__ encb,
                      const float* __restrict__ f1w,  const float* __restrict__ f1b,
                      const float* __restrict__ f2w,  const float* __restrict__ f2b,
                      const float* __restrict__ f3w,  const float* __restrict__ f3b,
                      const float* __restrict__ f4w,  const float* __restrict__ f4b,
                      const float* __restrict__ f5w,  const float* __restrict__ f5b,
                      const float* __restrict__ ow,   const float* __restrict__ ob,
                      float* __restrict__ out)
{
    extern __shared__ float sm[];
    const int b    = blockIdx.x;
    const int tid  = threadIdx.x;
    const int wrp  = tid >> 5;
    const int lane = tid & 31;

    // ---- zero padded regions, stage C tile + conv weights/biases ----
    for (int i = tid; i < XS_SZ; i += NTHREADS) sm[XS_OFF + i] = 0.f;
    for (int i = tid; i < H1_SZ; i += NTHREADS) sm[H1_OFF + i] = 0.f;
    for (int i = tid; i < WS1_SZ; i += NTHREADS) sm[WS1_OFF + i] = w1[i];
    if (tid < 32) sm[B1_OFF + tid] = b1[tid];
    if (tid < 64) sm[B2_OFF + tid] = b2[tid];
    for (int i = tid; i < CS_SZ; i += NTHREADS) sm[CS_OFF + i] = C[b * 2500 + i];
    __syncthreads();

    // ---- load input tile into padded+swizzled SMEM ----
    const float* xb = x + (size_t)b * (3 * 64 * 64);
    for (int i = tid; i < 3 * 64 * 64; i += NTHREADS) {
        int ic  = i >> 12;
        int rem = i & 4095;
        int y   = rem >> 6;
        int xc  = rem & 63;
        sm[xs_idx(ic, y + 1, xc + 1)] = xb[i];
    }
    __syncthreads();

    // =====================================================================
    // conv1: 3->32, k3 s2 p1, out 32x32.  warp w handles oc in [4w, 4w+4),
    // lane = ox, loop oy (tiled by 8 to keep weights in registers per ic).
    // =====================================================================
    {
        const int oc0 = wrp * 4;
        for (int oyt = 0; oyt < 4; oyt++) {
            float acc[8][4];
            #pragma unroll
            for (int q = 0; q < 8; q++)
                #pragma unroll
                for (int o = 0; o < 4; o++) acc[q][o] = sm[B1_OFF + oc0 + o];

            #pragma unroll
            for (int ic = 0; ic < 3; ic++) {
                float wr[4][9];
                #pragma unroll
                for (int o = 0; o < 4; o++)
                    #pragma unroll
                    for (int k = 0; k < 9; k++)
                        wr[o][k] = sm[WS1_OFF + (oc0 + o) * 27 + ic * 9 + k];

                #pragma unroll
                for (int q = 0; q < 8; q++) {
                    const int oy = oyt * 8 + q;
                    #pragma unroll
                    for (int ky = 0; ky < 3; ky++) {
                        const int r = 2 * oy + ky;   // padded row index
                        #pragma unroll
                        for (int kx = 0; kx < 3; kx++) {
                            const int c = 2 * lane + kx; // padded col index
                            const float v = sm[xs_idx(ic, r, c)];
                            #pragma unroll
                            for (int o = 0; o < 4; o++)
                                acc[q][o] = fmaf(v, wr[o][3 * ky + kx], acc[q][o]);
                        }
                    }
                }
            }
            #pragma unroll
            for (int q = 0; q < 8; q++) {
                const int oy = oyt * 8 + q;
                #pragma unroll
                for (int o = 0; o < 4; o++)
                    sm[h1_idx(oc0 + o, 1 + oy, 1 + lane)] = fmaxf(acc[q][o], 0.f);
            }
        }
    }
    __syncthreads();

    // =====================================================================
    // conv2: 32->64, k3 s2 p1, out 16x16, fused with relu + mean pool.
    // warp w owns oc in [8w, 8w+8) (two passes of 4).
    // lane: ox2 = lane&15, ybit = lane>>4; position j: oy2 = 2j + ybit.
    // =====================================================================
    {
        const int ybit  = lane >> 4;
        const int ox2   = lane & 15;
        const int cbase = 2 * ox2;        // padded col base

        for (int og = 0; og < 2; og++) {
            const int ocb = wrp * 8 + og * 4;
            float acc[4][8];
            #pragma unroll
            for (int o = 0; o < 4; o++)
                #pragma unroll
                for (int j = 0; j < 8; j++) acc[o][j] = sm[B2_OFF + ocb + o];

            for (int ic = 0; ic < 32; ic++) {
                float wr[4][9];
                #pragma unroll
                for (int o = 0; o < 4; o++)
                    #pragma unroll
                    for (int k = 0; k < 9; k++)
                        wr[o][k] = __ldg(&w2[((ocb + o) * 32 + ic) * 9 + k]);

                const float* hc = &sm[H1_OFF + ic * (34 * 35)];
                #pragma unroll
                for (int j = 0; j < 8; j++) {
                    const int oy2 = 2 * j + ybit;
                    #pragma unroll
                    for (int ky = 0; ky < 3; ky++) {
                        const int r    = 2 * oy2 + ky;        // padded row
                        const int flip = (r >> 1) & 1;
                        const float* row = hc + r * 35;
                        const float h0 = row[(cbase + 0) ^ flip];
                        const float h1v = row[(cbase + 1) ^ flip];
                        const float h2v = row[(cbase + 2) ^ flip];
                        #pragma unroll
                        for (int o = 0; o < 4; o++) {
                            acc[o][j] = fmaf(h0,  wr[o][3 * ky + 0], acc[o][j]);
                            acc[o][j] = fmaf(h1v, wr[o][3 * ky + 1], acc[o][j]);
                            acc[o][j] = fmaf(h2v, wr[o][3 * ky + 2], acc[o][j]);
                        }
                    }
                }
            }
            // relu + pool (sum 8 positions per lane, then warp reduce)
            #pragma unroll
            for (int o = 0; o < 4; o++) {
                float s = 0.f;
                #pragma unroll
                for (int j = 0; j < 8; j++) s += fmaxf(acc[o][j], 0.f);
                #pragma unroll
                for (int off = 16; off > 0; off >>= 1)
                    s += __shfl_xor_sync(0xffffffffu, s, off);
                if (lane == 0) sm[POOL_OFF + ocb + o] = s * (1.f / 256.f);
            }
        }
    }
    __syncthreads();

    // =====================================================================
    // MLP head (all vectors in SMEM, thread-per-neuron)
    // =====================================================================
    // x1 = relu(pool @ enc_w + enc_b)   [128]
    if (tid < 128) {
        float s = encb[tid];
        #pragma unroll
        for (int k = 0; k < 64; k++) s = fmaf(sm[POOL_OFF + k], __ldg(&encw[k * 128 + tid]), s);
        sm[X1_OFF + tid] = fmaxf(s, 0.f);
    }
    __syncthreads();
    // x2 = relu(x1 @ f1_w + f1_b)  [50]
    if (tid < NVAR) {
        float s = f1b[tid];
        #pragma unroll
        for (int k = 0; k < 128; k++) s = fmaf(sm[X1_OFF + k], __ldg(&f1w[k * NVAR + tid]), s);
        sm[X2_OFF + tid] = fmaxf(s, 0.f);
    }
    __syncthreads();
    // e = C[b] @ x2  [50]
    if (tid < NVAR) {
        float s = 0.f;
        #pragma unroll
        for (int k = 0; k < NVAR; k++) s = fmaf(sm[CS_OFF + tid * NVAR + k], sm[X2_OFF + k], s);
        sm[E_OFF + tid] = s;
    }
    __syncthreads();
    // x3 = relu(e @ f2_w + f2_b)  [128]
    if (tid < 128) {
        float s = f2b[tid];
        #pragma unroll
        for (int k = 0; k < NVAR; k++) s = fmaf(sm[E_OFF + k], __ldg(&f2w[k * 128 + tid]), s);
        sm[X3_OFF + tid] = fmaxf(s, 0.f);
    }
    __syncthreads();
    // x5 = relu(concat(x1,x3) @ f3_w + f3_b)  [64]
    if (tid < 64) {
        float s = f3b[tid];
        #pragma unroll
        for (int k = 0; k < 128; k++) s = fmaf(sm[X1_OFF + k], __ldg(&f3w[k * 64 + tid]), s);
        #pragma unroll
        for (int k = 0; k < 128; k++) s = fmaf(sm[X3_OFF + k], __ldg(&f3w[(128 + k) * 64 + tid]), s);
        sm[X5_OFF + tid] = fmaxf(s, 0.f);
    }
    __syncthreads();
    // x6 = relu(x5 @ f4_w + f4_b)  [64]
    if (tid < 64) {
        float s = f4b[tid];
        #pragma unroll
        for (int k = 0; k < 64; k++) s = fmaf(sm[X5_OFF + k], __ldg(&f4w[k * 64 + tid]), s);
        sm[X6_OFF + tid] = fmaxf(s, 0.f);
    }
    __syncthreads();
    // x7 = relu(x6 @ f5_w + f5_b)  [64]
    if (tid < 64) {
        float s = f5b[tid];
        #pragma unroll
        for (int k = 0; k < 64; k++) s = fmaf(sm[X6_OFF + k], __ldg(&f5w[k * 64 + tid]), s);
        sm[X7_OFF + tid] = fmaxf(s, 0.f);
    }
    __syncthreads();
    // logits = relu(x7 @ out_w + out_b)  [50]
    if (tid < NVAR) {
        float s = ob[tid];
        #pragma unroll
        for (int k = 0; k < 64; k++) s = fmaf(sm[X7_OFF + k], __ldg(&ow[k * NVAR + tid]), s);
        sm[LG_OFF + tid] = fmaxf(s, 0.f);
    }
    __syncthreads();
    // softmax over 50
    if (tid == 0) {
        float m = sm[LG_OFF];
        for (int i = 1; i < NVAR; i++) m = fmaxf(m, sm[LG_OFF + i]);
        sm[RED_OFF] = m;
    }
    __syncthreads();
    if (tid < NVAR) sm[LG_OFF + tid] = expf(sm[LG_OFF + tid] - sm[RED_OFF]);
    __syncthreads();
    if (tid == 0) {
        float s = 0.f;
        for (int i = 0; i < NVAR; i++) s += sm[LG_OFF + i];
        sm[RED_OFF + 1] = 1.f / s;
    }
    __syncthreads();
    if (tid < NVAR) out[b * NVAR + tid] = sm[LG_OFF + tid] * sm[RED_OFF + 1];
}

extern "C" void kernel_launch(void* const* d_in, const int* in_sizes, int n_in,
                              void* d_out, int out_size)
{
    (void)in_sizes; (void)n_in; (void)out_size;
    const float* x    = (const float*)d_in[0];
    const float* C    = (const float*)d_in[1];
    const float* w1   = (const float*)d_in[2];
    const float* b1   = (const float*)d_in[3];
    const float* w2   = (const float*)d_in[4];
    const float* b2   = (const float*)d_in[5];
    const float* encw = (const float*)d_in[6];
    const float* encb = (const float*)d_in[7];
    const float* f1w  = (const float*)d_in[8];
    const float* f1b  = (const float*)d_in[9];
    const float* f2w  = (const float*)d_in[10];
    const float* f2b  = (const float*)d_in[11];
    const float* f3w  = (const float*)d_in[12];
    const float* f3b  = (const float*)d_in[13];
    const float* f4w  = (const float*)d_in[14];
    const float* f4b  = (const float*)d_in[15];
    const float* f5w  = (const float*)d_in[16];
    const float* f5b  = (const float*)d_in[17];
    const float* ow   = (const float*)d_in[18];
    const float* ob   = (const float*)d_in[19];
    float* out = (float*)d_out;

    cudaFuncSetAttribute(gcp_fused_kernel,
                         cudaFuncAttributeMaxDynamicSharedMemorySize, SMEM_BYTES);

    gcp_fused_kernel<<<B_SAMPLES, NTHREADS, SMEM_BYTES>>>(
        x, C, w1, b1, w2, b2, encw, encb, f1w, f1b, f2w, f2b,
        f3w, f3b, f4w, f4b, f5w, f5b, ow, ob, out);
}

// round 2
// speedup vs baseline: 1.0633x; 1.0633x over previous
#include <cuda_runtime.h>

// ---------------------------------------------------------------------------
// Fused Goal_Conditioned_Policies forward: one CTA per sample (B = 4096).
// Banded pipeline: conv1/conv2 processed in 4 bands of 4 conv2-output rows so
// shared memory fits 2 CTAs/SM (occupancy fix vs round 1).
// conv1(3->32,s2) -> relu -> conv2(32->64,s2) -> relu -> meanpool -> MLP -> softmax
// ---------------------------------------------------------------------------

#define B_SAMPLES 4096
#define NVAR      50
#define NTHREADS  256

// conv2 weights pre-transposed to [ic][oc][12] (9 used + 3 pad) for aligned
// float4 loads. Rebuilt deterministically every launch.
__device__ __align__(16) float g_w2t[32 * 64 * 12];

__global__ void w2t_prep_kernel(const float* __restrict__ w2) {
    int i = blockIdx.x * blockDim.x + threadIdx.x;   // over 32*64 = 2048
    if (i < 2048) {
        int ic = i >> 6, oc = i & 63;
        float* dst = &g_w2t[ic * 768 + oc * 12];
        const float* src = &w2[(oc * 32 + ic) * 9];
        #pragma unroll
        for (int k = 0; k < 9; k++) dst[k] = src[k];
        dst[9] = dst[10] = dst[11] = 0.f;
    }
}

// ---- shared memory layout (floats) ----
#define XB_OFF   0                      // x band [3][19][67]
#define XB_SZ    (3 * 19 * 67)          // 3819
#define H1B_OFF  (XB_OFF + XB_SZ)       // h1 band [32][9][35]
#define H1B_SZ   (32 * 9 * 35)          // 10080
#define CS_OFF   (H1B_OFF + H1B_SZ)     // C[b] 50x50
#define CS_SZ    2500
#define WS1_OFF  (CS_OFF + CS_SZ)       // conv1 weights 32*3*9
#define WS1_SZ   864
#define B1_OFF   (WS1_OFF + WS1_SZ)
#define B2_OFF   (B1_OFF + 32)
#define POOL_OFF (B2_OFF + 64)
#define X1_OFF   (POOL_OFF + 64)
#define X2_OFF   (X1_OFF + 128)
#define E_OFF    (X2_OFF + 64)
#define X3_OFF   (E_OFF + 64)
#define X5_OFF   (X3_OFF + 128)
#define X6_OFF   (X5_OFF + 64)
#define X7_OFF   (X6_OFF + 64)
#define LG_OFF   (X7_OFF + 64)
#define RED_OFF  (LG_OFF + 64)
#define SMEM_FLOATS (RED_OFF + 4)
#define SMEM_BYTES  (SMEM_FLOATS * 4)   // ~72.3 KB -> 2 CTAs/SM

__global__ __launch_bounds__(NTHREADS, 2)
void gcp_fused_kernel(const float* __restrict__ x,    const float* __restrict__ C,
                      const float* __restrict__ w1,   const float* __restrict__ b1,
                      const float* __restrict__ b2,
                      const float* __restrict__ encw, const float* __restrict__ encb,
                      const float* __restrict__ f1w,  const float* __restrict__ f1b,
                      const float* __restrict__ f2w,  const float* __restrict__ f2b,
                      const float* __restrict__ f3w,  const float* __restrict__ f3b,
                      const float* __restrict__ f4w,  const float* __restrict__ f4b,
                      const float* __restrict__ f5w,  const float* __restrict__ f5b,
                      const float* __restrict__ ow,   const float* __restrict__ ob,
                      float* __restrict__ out)
{
    extern __shared__ float sm[];
    const int b    = blockIdx.x;
    const int tid  = threadIdx.x;
    const int wrp  = tid >> 5;
    const int lane = tid & 31;

    // ---- one-time init: zero band buffers (pads must stay 0), stage C/w1/biases ----
    for (int i = tid; i < XB_SZ + H1B_SZ; i += NTHREADS) sm[i] = 0.f;
    for (int i = tid; i < WS1_SZ; i += NTHREADS) sm[WS1_OFF + i] = w1[i];
    if (tid < 32) sm[B1_OFF + tid] = b1[tid];
    if (tid < 64) sm[B2_OFF + tid] = b2[tid];
    for (int i = tid; i < CS_SZ; i += NTHREADS) sm[CS_OFF + i] = C[b * 2500 + i];

    const float* xb = x + (size_t)b * (3 * 64 * 64);

    const int halfq = lane >> 4;   // conv2: which of 2 row-groups in half-warp
    const int cx    = lane & 15;   // conv2 output column
    const int oc2b  = wrp * 8;     // conv2: 8 output channels per warp
    const int oc1b  = wrp * 4;     // conv1: 4 output channels per warp

    float pool_acc[8];
    #pragma unroll
    for (int o = 0; o < 8; o++) pool_acc[o] = 0.f;

    // =====================================================================
    // 4 bands; band t covers conv2 output rows [4t, 4t+4)
    //   needs h1 rows r1 in [8t-1, 8t+7] (9 rows, local j = r1-(8t-1))
    //   needs x  rows xr in [16t-3, 16t+15] (19 rows, local i = xr-(16t-3))
    // =====================================================================
    for (int t = 0; t < 4; t++) {
        __syncthreads();   // prior band's conv2 reads done; buffers writable

        // ---- load x band (zero rows outside [0,64)) ----
        for (int i = tid; i < 3 * 19 * 64; i += NTHREADS) {
            int ic  = i / (19 * 64);
            int rem = i - ic * (19 * 64);
            int r   = rem >> 6;
            int c   = rem & 63;
            int xr  = 16 * t - 3 + r;
            float v = (xr >= 0 && xr < 64) ? xb[ic * 4096 + xr * 64 + c] : 0.f;
            int cp  = c + 1;
            sm[XB_OFF + ic * (19 * 67) + r * 67 + (cp ^ ((cp >> 5) & 1))] = v;
        }
        __syncthreads();

        // ---- conv1 band: h1 rows j=0..8, warp owns 4 oc, lane = col ----
        {
            float a1[9][4];
            #pragma unroll
            for (int j = 0; j < 9; j++)
                #pragma unroll
                for (int o = 0; o < 4; o++) a1[j][o] = sm[B1_OFF + oc1b + o];

            #pragma unroll
            for (int ic = 0; ic < 3; ic++) {
                float wr1[4][9];
                #pragma unroll
                for (int o = 0; o < 4; o++)
                    #pragma unroll
                    for (int k = 0; k < 9; k++)
                        wr1[o][k] = sm[WS1_OFF + (oc1b + o) * 27 + ic * 9 + k];

                const float* xc = &sm[XB_OFF + ic * (19 * 67)];
                #pragma unroll
                for (int j = 0; j < 9; j++) {
                    #pragma unroll
                    for (int ky = 0; ky < 3; ky++) {
                        const float* row = xc + (2 * j + ky) * 67;
                        #pragma unroll
                        for (int kx = 0; kx < 3; kx++) {
                            int cp = 2 * lane + kx;
                            float v = row[cp ^ ((cp >> 5) & 1)];
                            #pragma unroll
                            for (int o = 0; o < 4; o++)
                                a1[j][o] = fmaf(v, wr1[o][3 * ky + kx], a1[j][o]);
                        }
                    }
                }
            }
            #pragma unroll
            for (int j = 0; j < 9; j++) {
                int r1 = 8 * t - 1 + j;
                bool valid = (unsigned)r1 < 32u;
                int flip = (j >> 1) & 1;
                #pragma unroll
                for (int o = 0; o < 4; o++)
                    sm[H1B_OFF + (oc1b + o) * 315 + j * 35 + ((1 + lane) ^ flip)]
                        = valid ? fmaxf(a1[j][o], 0.f) : 0.f;
            }
        }
        __syncthreads();

        // ---- conv2 band: 64 positions (4 rows x 16 cols), warp owns 8 oc ----
        // lane position p: out row q = halfq + 2p, col cx. h1 local row j = 2q+ky.
        {
            float a2[8][2];
            #pragma unroll
            for (int o = 0; o < 8; o++) {
                float bb = sm[B2_OFF + oc2b + o];
                a2[o][0] = bb; a2[o][1] = bb;
            }

            #pragma unroll 1
            for (int ic = 0; ic < 32; ic++) {
                const float4* wp = (const float4*)(g_w2t + ic * 768 + oc2b * 12);
                float wr[8][9];
                #pragma unroll
                for (int o = 0; o < 8; o++) {
                    float4 u0 = wp[o * 3 + 0];
                    float4 u1 = wp[o * 3 + 1];
                    float4 u2 = wp[o * 3 + 2];
                    wr[o][0] = u0.x; wr[o][1] = u0.y; wr[o][2] = u0.z;
                    wr[o][3] = u0.w; wr[o][4] = u1.x; wr[o][5] = u1.y;
                    wr[o][6] = u1.z; wr[o][7] = u1.w; wr[o][8] = u2.x;
                }
                const float* hc = &sm[H1B_OFF + ic * 315];
                #pragma unroll
                for (int p = 0; p < 2; p++) {
                    const int q = halfq + 2 * p;
                    #pragma unroll
                    for (int ky = 0; ky < 3; ky++) {
                        const int j = 2 * q + ky;
                        const int flip = (j >> 1) & 1;
                        const float* row = hc + j * 35;
                        const int cb = 2 * cx;
                        float t0 = row[(cb + 0) ^ flip];
                        float t1 = row[(cb + 1) ^ flip];
                        float t2 = row[(cb + 2) ^ flip];
                        #pragma unroll
                        for (int o = 0; o < 8; o++) {
                            a2[o][p] = fmaf(t0, wr[o][3 * ky + 0], a2[o][p]);
                            a2[o][p] = fmaf(t1, wr[o][3 * ky + 1], a2[o][p]);
                            a2[o][p] = fmaf(t2, wr[o][3 * ky + 2], a2[o][p]);
                        }
                    }
                }
            }
            #pragma unroll
            for (int o = 0; o < 8; o++)
                pool_acc[o] += fmaxf(a2[o][0], 0.f) + fmaxf(a2[o][1], 0.f);
        }
    }
    __syncthreads();

    // ---- pool: reduce each warp's 8 oc across lanes ----
    #pragma unroll
    for (int o = 0; o < 8; o++) {
        float s = pool_acc[o];
        #pragma unroll
        for (int off = 16; off > 0; off >>= 1)
            s += __shfl_xor_sync(0xffffffffu, s, off);
        if (lane == 0) sm[POOL_OFF + oc2b + o] = s * (1.f / 256.f);
    }
    __syncthreads();

    // =====================================================================
    // MLP head
    // =====================================================================
    if (tid < 128) {
        float s = encb[tid];
        #pragma unroll
        for (int k = 0; k < 64; k++) s = fmaf(sm[POOL_OFF + k], __ldg(&encw[k * 128 + tid]), s);
        sm[X1_OFF + tid] = fmaxf(s, 0.f);
    }
    __syncthreads();
    if (tid < NVAR) {
        float s = f1b[tid];
        #pragma unroll
        for (int k = 0; k < 128; k++) s = fmaf(sm[X1_OFF + k], __ldg(&f1w[k * NVAR + tid]), s);
        sm[X2_OFF + tid] = fmaxf(s, 0.f);
    }
    __syncthreads();
    if (tid < NVAR) {
        float s = 0.f;
        #pragma unroll
        for (int k = 0; k < NVAR; k++) s = fmaf(sm[CS_OFF + tid * NVAR + k], sm[X2_OFF + k], s);
        sm[E_OFF + tid] = s;
    }
    __syncthreads();
    if (tid < 128) {
        float s = f2b[tid];
        #pragma unroll
        for (int k = 0; k < NVAR; k++) s = fmaf(sm[E_OFF + k], __ldg(&f2w[k * 128 + tid]), s);
        sm[X3_OFF + tid] = fmaxf(s, 0.f);
    }
    __syncthreads();
    if (tid < 64) {
        float s = f3b[tid];
        #pragma unroll
        for (int k = 0; k < 128; k++) s = fmaf(sm[X1_OFF + k], __ldg(&f3w[k * 64 + tid]), s);
        #pragma unroll
        for (int k = 0; k < 128; k++) s = fmaf(sm[X3_OFF + k], __ldg(&f3w[(128 + k) * 64 + tid]), s);
        sm[X5_OFF + tid] = fmaxf(s, 0.f);
    }
    __syncthreads();
    if (tid < 64) {
        float s = f4b[tid];
        #pragma unroll
        for (int k = 0; k < 64; k++) s = fmaf(sm[X5_OFF + k], __ldg(&f4w[k * 64 + tid]), s);
        sm[X6_OFF + tid] = fmaxf(s, 0.f);
    }
    __syncthreads();
    if (tid < 64) {
        float s = f5b[tid];
        #pragma unroll
        for (int k = 0; k < 64; k++) s = fmaf(sm[X6_OFF + k], __ldg(&f5w[k * 64 + tid]), s);
        sm[X7_OFF + tid] = fmaxf(s, 0.f);
    }
    __syncthreads();
    if (tid < NVAR) {
        float s = ob[tid];
        #pragma unroll
        for (int k = 0; k < 64; k++) s = fmaf(sm[X7_OFF + k], __ldg(&ow[k * NVAR + tid]), s);
        sm[LG_OFF + tid] = fmaxf(s, 0.f);
    }
    __syncthreads();
    if (tid == 0) {
        float m = sm[LG_OFF];
        for (int i = 1; i < NVAR; i++) m = fmaxf(m, sm[LG_OFF + i]);
        sm[RED_OFF] = m;
    }
    __syncthreads();
    if (tid < NVAR) sm[LG_OFF + tid] = expf(sm[LG_OFF + tid] - sm[RED_OFF]);
    __syncthreads();
    if (tid == 0) {
        float s = 0.f;
        for (int i = 0; i < NVAR; i++) s += sm[LG_OFF + i];
        sm[RED_OFF + 1] = 1.f / s;
    }
    __syncthreads();
    if (tid < NVAR) out[b * NVAR + tid] = sm[LG_OFF + tid] * sm[RED_OFF + 1];
}

extern "C" void kernel_launch(void* const* d_in, const int* in_sizes, int n_in,
                              void* d_out, int out_size)
{
    (void)in_sizes; (void)n_in; (void)out_size;
    const float* x    = (const float*)d_in[0];
    const float* C    = (const float*)d_in[1];
    const float* w1   = (const float*)d_in[2];
    const float* b1   = (const float*)d_in[3];
    const float* w2   = (const float*)d_in[4];
    const float* b2   = (const float*)d_in[5];
    const float* encw = (const float*)d_in[6];
    const float* encb = (const float*)d_in[7];
    const float* f1w  = (const float*)d_in[8];
    const float* f1b  = (const float*)d_in[9];
    const float* f2w  = (const float*)d_in[10];
    const float* f2b  = (const float*)d_in[11];
    const float* f3w  = (const float*)d_in[12];
    const float* f3b  = (const float*)d_in[13];
    const float* f4w  = (const float*)d_in[14];
    const float* f4b  = (const float*)d_in[15];
    const float* f5w  = (const float*)d_in[16];
    const float* f5b  = (const float*)d_in[17];
    const float* ow   = (const float*)d_in[18];
    const float* ob   = (const float*)d_in[19];
    float* out = (float*)d_out;

    w2t_prep_kernel<<<8, 256>>>(w2);

    cudaFuncSetAttribute(gcp_fused_kernel,
                         cudaFuncAttributeMaxDynamicSharedMemorySize, SMEM_BYTES);

    gcp_fused_kernel<<<B_SAMPLES, NTHREADS, SMEM_BYTES>>>(
        x, C, w1, b1, b2, encw, encb, f1w, f1b, f2w, f2b,
        f3w, f3b, f4w, f4b, f5w, f5b, ow, ob, out);
}